// round 11
// baseline (speedup 1.0000x reference)
#include <cuda_runtime.h>
#include <cuda_bf16.h>

// FocalLossAdaptive: input [N=8192, C=32000] fp32, target [N] int -> scalar mean loss.
// Each row split across 2 CTAs of 128 threads (grid=16384): half the work per
// schedulable quantum at unchanged occupancy -> smaller end-of-kernel straggler tail.
// Per-row combine: atomicAdd's return value elects the row finisher (partial S > 0
// always, so old==0 <=> first arrival). Finisher computes the focal loss, RED.ADDs
// into g_sum; a global ticket elects the mean writer. No threadfence/CCTL.IVALL.

#define NROWS 8192
#define NCOLS 32000
#define NVEC  (NCOLS / 4)        // 8000 float4 per row
#define TPB   128
#define HALF_VEC (NVEC / 2)      // 4000 float4 per half-row = 31*128 + 32
#define FULL_ITERS 31
#define TAIL_THREADS 32

__device__ float    g_rowS[NROWS];   // zero-initialized; finisher resets to 0
__device__ float    g_sum = 0.0f;
__device__ unsigned g_ticket = 0;

// Targets may be serialized as int32 or little-endian int64. Probe: if int64,
// the odd 32-bit words (high halves of values < 32000) are all zero.
__device__ __forceinline__ int load_target(const int* __restrict__ t32, int row) {
    bool is64 = true;
    #pragma unroll
    for (int i = 0; i < 16; i++) is64 &= (t32[2 * i + 1] == 0);
    int t = is64 ? t32[2 * row] : t32[row];
    return (t < 0) ? 0 : (t >= NCOLS ? NCOLS - 1 : t);
}

__device__ __forceinline__ unsigned atom_add_acqrel_gpu_u32(unsigned* p, unsigned v) {
    unsigned old;
    asm volatile("atom.add.acq_rel.gpu.u32 %0, [%1], %2;"
                 : "=r"(old) : "l"(p), "r"(v) : "memory");
    return old;
}

__device__ __forceinline__ float atom_add_acqrel_gpu_f32(float* p, float v) {
    float old;
    asm volatile("atom.add.acq_rel.gpu.f32 %0, [%1], %2;"
                 : "=f"(old) : "l"(p), "f"(v) : "memory");
    return old;
}

__global__ __launch_bounds__(TPB) void focal_rows_kernel(const float* __restrict__ inp,
                                                         const int* __restrict__ tgt,
                                                         float* __restrict__ out) {
    const int row  = blockIdx.x >> 1;
    const int half = blockIdx.x & 1;
    const float* __restrict__ p = inp + (size_t)row * NCOLS;
    const float4* __restrict__ p4 = (const float4*)p + half * HALF_VEC;
    const int tid = threadIdx.x;

    // Plain sum of exp over this half-row; two accumulators.
    float s0 = 0.0f, s1 = 0.0f;

    int i = tid;
    #pragma unroll 4
    for (int it = 0; it < FULL_ITERS; ++it, i += TPB) {
        float4 v = __ldcs(p4 + i);          // streamed: touched exactly once
        s0 += __expf(v.x) + __expf(v.y);
        s1 += __expf(v.z) + __expf(v.w);
    }
    if (tid < TAIL_THREADS) {
        float4 v = __ldcs(p4 + FULL_ITERS * TPB + tid);
        s0 += __expf(v.x) + __expf(v.y);
        s1 += __expf(v.z) + __expf(v.w);
    }
    float s = s0 + s1;

    // Warp-level sum
    #pragma unroll
    for (int k = 16; k > 0; k >>= 1)
        s += __shfl_xor_sync(0xffffffffu, s, k);

    __shared__ float shs[TPB / 32];
    const int warp = tid >> 5;
    const int lane = tid & 31;
    if (lane == 0) shs[warp] = s;
    __syncthreads();

    __shared__ bool is_last;
    if (tid == 0) {
        float Sh = shs[0];
        #pragma unroll
        for (int w = 1; w < TPB / 32; w++) Sh += shs[w];

        bool last_cta = false;

        // Fold this half's partial into the row slot; old>0 means peer already
        // deposited (partial sums of exps are strictly positive) -> we finish the row.
        float old = atom_add_acqrel_gpu_f32(&g_rowS[row], Sh);
        if (old != 0.0f) {
            float S = old + Sh;
            int t = load_target(tgt, row);
            float xt = __ldg(p + t);
            float logpt = xt - logf(S);    // accurate log on the scalar path
            float pt = __expf(logpt);
            float u  = 1.0f - pt;
            float u3 = u * u * u;
            // gamma: 5 iff pt < 0.2, else 3
            float w_ = (pt < 0.2f) ? u3 * u * u : u3;

            atomicAdd(&g_sum, -w_ * logpt);    // RED.ADD.F32 via L2
            g_rowS[row] = 0.0f;                // reset slot for next graph replay

            // Row done: bump the global ticket (release orders the stores above).
            unsigned v = atom_add_acqrel_gpu_u32(&g_ticket, 1u);
            last_cta = (v == NROWS - 1);
        }
        is_last = last_cta;
    }
    __syncthreads();

    if (is_last && tid == 0) {
        float total;
        asm volatile("ld.global.acquire.gpu.f32 %0, [%1];" : "=f"(total) : "l"(&g_sum));
        out[0] = total * (1.0f / (float)NROWS);
        g_sum = 0.0f;                          // reset for next graph replay
        g_ticket = 0;
    }
}

extern "C" void kernel_launch(void* const* d_in, const int* in_sizes, int n_in,
                              void* d_out, int out_size) {
    const float* inp = (const float*)d_in[0];
    const int*   tgt = (const int*)d_in[1];
    float*       out = (float*)d_out;

    focal_rows_kernel<<<NROWS * 2, TPB>>>(inp, tgt, out);
}